// round 1
// baseline (speedup 1.0000x reference)
#include <cuda_runtime.h>

// ImageWarpingLayer: out = bilinear_sample(image, grid + flow)
// image: [B=16, H=512, W=512, C=8] f32   flow: [B, H, W, 2] f32 (dy, dx)
// Matches TF dense_image_warp semantics: floor clamped to [0, size-2],
// alpha = clip(q - floor, 0, 1).

#define Bn 16
#define Hn 512
#define Wn 512
#define Cn 8

__global__ __launch_bounds__(256, 8)
void warp_kernel(const float* __restrict__ image,
                 const float* __restrict__ flow,
                 float* __restrict__ out)
{
    const int idx = blockIdx.x * blockDim.x + threadIdx.x; // pixel id: ((b*H + y)*W + x)
    // total = 16*512*512 = 4194304, grid sized exactly -> no bounds check needed,
    // but keep it cheap and safe:
    const int x = idx & (Wn - 1);
    const int y = (idx >> 9) & (Hn - 1);

    // flow is [.., 2] contiguous -> float2 per pixel, 8B aligned
    const float2 f = reinterpret_cast<const float2*>(flow)[idx];
    const float qy = (float)y + f.x;
    const float qx = (float)x + f.y;

    // floor clamped to [0, size-2] (TF impl), THEN alpha = clip(q - floor, 0, 1)
    const float fy = fminf(fmaxf(floorf(qy), 0.0f), (float)(Hn - 2));
    const float fx = fminf(fmaxf(floorf(qx), 0.0f), (float)(Wn - 2));
    const float ay = fminf(fmaxf(qy - fy, 0.0f), 1.0f);
    const float ax = fminf(fmaxf(qx - fx, 0.0f), 1.0f);

    const int iy = (int)fy;
    const int ix = (int)fx;
    const int b  = idx >> 18; // / (H*W)

    // base of image[b, iy, ix, 0]; tl..tr span = 2*C = 16 floats contiguous
    const long top = (((long)b * Hn + iy) * Wn + ix) * Cn;
    const long bot = top + (long)Wn * Cn;

    const float4* __restrict__ pt = reinterpret_cast<const float4*>(image + top);
    const float4* __restrict__ pb = reinterpret_cast<const float4*>(image + bot);

    // top-left (2x float4), top-right (2x float4)
    const float4 tl0 = pt[0], tl1 = pt[1];
    const float4 tr0 = pt[2], tr1 = pt[3];
    const float4 bl0 = pb[0], bl1 = pb[1];
    const float4 br0 = pb[2], br1 = pb[3];

    float4 o0, o1;
    {
        // lerp in x on top and bottom, then lerp in y
        float t, bo;
        t  = tl0.x + ax * (tr0.x - tl0.x);
        bo = bl0.x + ax * (br0.x - bl0.x);
        o0.x = t + ay * (bo - t);
        t  = tl0.y + ax * (tr0.y - tl0.y);
        bo = bl0.y + ax * (br0.y - bl0.y);
        o0.y = t + ay * (bo - t);
        t  = tl0.z + ax * (tr0.z - tl0.z);
        bo = bl0.z + ax * (br0.z - bl0.z);
        o0.z = t + ay * (bo - t);
        t  = tl0.w + ax * (tr0.w - tl0.w);
        bo = bl0.w + ax * (br0.w - bl0.w);
        o0.w = t + ay * (bo - t);

        t  = tl1.x + ax * (tr1.x - tl1.x);
        bo = bl1.x + ax * (br1.x - bl1.x);
        o1.x = t + ay * (bo - t);
        t  = tl1.y + ax * (tr1.y - tl1.y);
        bo = bl1.y + ax * (br1.y - bl1.y);
        o1.y = t + ay * (bo - t);
        t  = tl1.z + ax * (tr1.z - tl1.z);
        bo = bl1.z + ax * (br1.z - bl1.z);
        o1.z = t + ay * (bo - t);
        t  = tl1.w + ax * (tr1.w - tl1.w);
        bo = bl1.w + ax * (br1.w - bl1.w);
        o1.w = t + ay * (bo - t);
    }

    float4* __restrict__ po = reinterpret_cast<float4*>(out + (long)idx * Cn);
    po[0] = o0;
    po[1] = o1;
}

extern "C" void kernel_launch(void* const* d_in, const int* in_sizes, int n_in,
                              void* d_out, int out_size)
{
    const float* image = (const float*)d_in[0];
    const float* flow  = (const float*)d_in[1];
    float* out = (float*)d_out;

    const int total_pixels = Bn * Hn * Wn; // 4194304
    const int threads = 256;
    const int blocks = total_pixels / threads; // 16384
    warp_kernel<<<blocks, threads>>>(image, flow, out);
}

// round 2
// speedup vs baseline: 1.2740x; 1.2740x over previous
#include <cuda_runtime.h>

// ImageWarpingLayer: out = bilinear_sample(image, grid + flow)
// image: [B=16, H=512, W=512, C=8] f32   flow: [B, H, W, 2] f32 (dy, dx)
// TF dense_image_warp semantics: floor clamped to [0, size-2],
// alpha = clip(q - floor, 0, 1).
//
// Layout: 2 threads per pixel; each thread owns one float4 half of the
// C=8 channel vector. This makes each corner gather a single LDG.128 whose
// warp-lane addresses are nearly contiguous (~512B span for 16 pixels),
// cutting l1tex wavefront replays vs the 1-thread/pixel scheme.

#define Bn 16
#define Hn 512
#define Wn 512
#define Cn 8

__global__ __launch_bounds__(256, 8)
void warp_kernel(const float* __restrict__ image,
                 const float* __restrict__ flow,
                 float* __restrict__ out)
{
    const int tid  = blockIdx.x * blockDim.x + threadIdx.x; // 2 threads per pixel
    const int pix  = tid >> 1;          // pixel id: ((b*H + y)*W + x)
    const int half = tid & 1;           // which float4 half of the channels

    const int x = pix & (Wn - 1);
    const int y = (pix >> 9) & (Hn - 1);
    const int b = pix >> 18;

    // flow is [.., 2] contiguous -> float2 per pixel (lane pairs share the
    // same address; duplicate sectors coalesce in L1)
    const float2 f = reinterpret_cast<const float2*>(flow)[pix];
    const float qy = (float)y + f.x;
    const float qx = (float)x + f.y;

    // floor clamped to [0, size-2] (TF impl), THEN alpha = clip(q-floor, 0, 1)
    const float fy = fminf(fmaxf(floorf(qy), 0.0f), (float)(Hn - 2));
    const float fx = fminf(fmaxf(floorf(qx), 0.0f), (float)(Wn - 2));
    const float ay = fminf(fmaxf(qy - fy, 0.0f), 1.0f);
    const float ax = fminf(fmaxf(qx - fx, 0.0f), 1.0f);

    const int iy = (int)fy;
    const int ix = (int)fx;

    // base of image[b, iy, ix, half*4]; tr is +C floats, bottom is +W*C floats
    const long top = (((long)b * Hn + iy) * Wn + ix) * Cn + half * 4;
    const long bot = top + (long)Wn * Cn;

    const float4 tl = *reinterpret_cast<const float4*>(image + top);
    const float4 tr = *reinterpret_cast<const float4*>(image + top + Cn);
    const float4 bl = *reinterpret_cast<const float4*>(image + bot);
    const float4 br = *reinterpret_cast<const float4*>(image + bot + Cn);

    float4 o;
    {
        float t, bo;
        t   = fmaf(ax, tr.x - tl.x, tl.x);
        bo  = fmaf(ax, br.x - bl.x, bl.x);
        o.x = fmaf(ay, bo - t, t);
        t   = fmaf(ax, tr.y - tl.y, tl.y);
        bo  = fmaf(ax, br.y - bl.y, bl.y);
        o.y = fmaf(ay, bo - t, t);
        t   = fmaf(ax, tr.z - tl.z, tl.z);
        bo  = fmaf(ax, br.z - bl.z, bl.z);
        o.z = fmaf(ay, bo - t, t);
        t   = fmaf(ax, tr.w - tl.w, tl.w);
        bo  = fmaf(ax, br.w - bl.w, bl.w);
        o.w = fmaf(ay, bo - t, t);
    }

    // out[pix*8 + half*4] == out[tid*4] -> perfectly coalesced STG.128
    reinterpret_cast<float4*>(out)[tid] = o;
}

extern "C" void kernel_launch(void* const* d_in, const int* in_sizes, int n_in,
                              void* d_out, int out_size)
{
    const float* image = (const float*)d_in[0];
    const float* flow  = (const float*)d_in[1];
    float* out = (float*)d_out;

    const int total_threads = Bn * Hn * Wn * 2; // 8388608 (2 per pixel)
    const int threads = 256;
    const int blocks = total_threads / threads; // 32768
    warp_kernel<<<blocks, threads>>>(image, flow, out);
}